// round 17
// baseline (speedup 1.0000x reference)
#include <cuda_runtime.h>
#include <cstdint>
#include <cstddef>

#define S    512
#define TT   2048
#define NB   16
#define CLU  8
#define CPC  64          // columns per CTA
#define NTHR 256         // 8 warps, 8 cols per warp
#define LN_EPS 1e-5f

typedef unsigned long long ull;

// Per-step inbound bytes per CTA: z 8CTA*8warp*4*8B = 2048, part 8*8*8B = 512
#define STEP_TX_BYTES 2560u

// ---------------- scratch (allocation-free rule: __device__ globals) ----------
__device__ float g_bufU[(size_t)NB * TT * S];   // 64MB
__device__ float g_bufH[(size_t)NB * TT * S];   // 64MB
__device__ float g_W01[(size_t)S * S];          // 1MB

// ---------------- PTX helpers -------------------------------------------------
__device__ __forceinline__ uint32_t smem_u32(const void* p) {
    return (uint32_t)__cvta_generic_to_shared(p);
}
__device__ __forceinline__ uint32_t mapa_shared(uint32_t addr, int rank) {
    uint32_t out;
    asm("mapa.shared::cluster.u32 %0, %1, %2;" : "=r"(out) : "r"(addr), "r"(rank));
    return out;
}
// st.async: data + tx-completion delivered to the REMOTE CTA's mbarrier.
__device__ __forceinline__ void st_async_b64(uint32_t dst, ull v, uint32_t mbar) {
    asm volatile(
        "st.async.shared::cluster.mbarrier::complete_tx::bytes.b64 [%0], %1, [%2];"
        :: "r"(dst), "l"(v), "r"(mbar) : "memory");
}
__device__ __forceinline__ void mbar_init(uint32_t addr, uint32_t cnt) {
    asm volatile("mbarrier.init.shared.b64 [%0], %1;" :: "r"(addr), "r"(cnt) : "memory");
}
__device__ __forceinline__ void mbar_expect_tx(uint32_t addr, uint32_t bytes) {
    asm volatile("mbarrier.arrive.expect_tx.shared.b64 _, [%0], %1;"
                 :: "r"(addr), "r"(bytes) : "memory");
}
__device__ __forceinline__ void mbar_wait_parity(uint32_t addr, uint32_t phase) {
    uint32_t done = 0;
    while (!done) {
        asm volatile(
            "{\n\t.reg .pred p;\n\t"
            "mbarrier.try_wait.parity.acquire.cta.shared::cta.b64 p, [%1], %2, 0x989680;\n\t"
            "selp.b32 %0, 1, 0, p;\n\t}"
            : "=r"(done) : "r"(addr), "r"(phase) : "memory");
    }
}
__device__ __forceinline__ void cluster_barrier() {
    asm volatile("barrier.cluster.arrive.aligned;" ::: "memory");
    asm volatile("barrier.cluster.wait.aligned;"  ::: "memory");
}
__device__ __forceinline__ ull pk(float x, float y) {
    ull r; asm("mov.b64 %0, {%1, %2};" : "=l"(r) : "f"(x), "f"(y)); return r;
}
__device__ __forceinline__ float2 upk(ull v) {
    float2 r; asm("mov.b64 {%0, %1}, %2;" : "=f"(r.x), "=f"(r.y) : "l"(v)); return r;
}
__device__ __forceinline__ ull ffma2(ull a, ull b, ull c) {
    ull d; asm("fma.rn.f32x2 %0, %1, %2, %3;" : "=l"(d) : "l"(a), "l"(b), "l"(c)); return d;
}

// ---------------- scan kernel (VERBATIM R5 — best measured) -------------------
// grid = 128 CTAs = 16 clusters of 8. Cluster c = batch c.
// Per step: FFMA2 matmul -> butterfly reduce -> lanes 0-7 st.async packed z +
// LN partials to every rank (tx-counted on the remote mbarrier) -> local
// parity wait (acquire.cta) -> tid0 re-arms expect_tx for t+2 -> per-warp
// redundant LN reduce -> LN+GELU; h in regs, mirrored in SMEM. 1 sync/step.
extern __shared__ float sm[];

#define A_OFF   16
#define H_OFF   (A_OFF + CPC * S)          // 16 + 32768
#define ZB_OFF  (H_OFF + S)                // + 512
#define P_OFF   (ZB_OFF + 2 * S)           // + 1024
#define SM_FLTS (P_OFF + 2 * 64 * 2)       // + 256
static const size_t SCAN_SMEM = (size_t)SM_FLTS * sizeof(float);

__global__ void __cluster_dims__(CLU, 1, 1) __launch_bounds__(NTHR, 1)
scan_kernel(const float* __restrict__ Aw, const float* __restrict__ Kw,
            const float* __restrict__ ab, const float* __restrict__ gg,
            const float* __restrict__ bb, const float* __restrict__ U,
            float* __restrict__ HS)
{
    float* A_sm = sm + A_OFF;              // [64][512]
    float* h_sm = sm + H_OFF;              // [512]
    float* zb   = sm + ZB_OFF;             // [2][512]
    float* part = sm + P_OFF;              // [2][64][2]

    const uint32_t mbar_u = smem_u32(sm);  // mbar[0] at +0, mbar[1] at +8
    const int tid  = threadIdx.x;
    const int lane = tid & 31;
    const int w    = tid >> 5;             // warp 0..7
    const int batch = blockIdx.x / CLU;
    const int rank  = blockIdx.x % CLU;
    const int colbase = rank * CPC;
    const int wcol = colbase + 8 * w;      // first global col of this warp

    if (tid == 0) {
        mbar_init(mbar_u, 1);
        mbar_init(mbar_u + 8, 1);
        mbar_expect_tx(mbar_u,     STEP_TX_BYTES);
        mbar_expect_tx(mbar_u + 8, STEP_TX_BYTES);
    }

    // A slice: A_sm[c][j] = Aw[j*S + colbase + c]
    for (int idx = tid; idx < CPC * S; idx += NTHR) {
        int j = idx >> 6, c = idx & 63;
        A_sm[c * S + j] = Aw[(size_t)j * S + colbase + c];
    }
    for (int i = tid; i < S; i += NTHR) h_sm[i] = 0.f;

    // K packed: kp[c][r][p] = (K[k0+2p][wcol+c], K[k0+2p+1][wcol+c]), k0=4*lane+128*r
    ull kp[8][4][2];
#pragma unroll
    for (int c = 0; c < 8; c++)
#pragma unroll
        for (int r = 0; r < 4; r++) {
            int k0 = 4 * lane + 128 * r;
            kp[c][r][0] = pk(Kw[(size_t)(k0 + 0) * S + wcol + c],
                             Kw[(size_t)(k0 + 1) * S + wcol + c]);
            kp[c][r][1] = pk(Kw[(size_t)(k0 + 2) * S + wcol + c],
                             Kw[(size_t)(k0 + 3) * S + wcol + c]);
        }
    float abv[8];
#pragma unroll
    for (int c = 0; c < 8; c++) abv[c] = ab[wcol + c];

    const float2 g2 = *(const float2*)&gg[2 * tid];
    const float2 b2 = *(const float2*)&bb[2 * tid];
    float2 hreg = make_float2(0.f, 0.f);

    // per-lane remote addresses (lane L -> rank L)
    const int rr = lane & 7;
    const uint32_t zdst = mapa_shared(smem_u32(zb), rr);
    const uint32_t pdst = mapa_shared(smem_u32(part), rr);
    const uint32_t mdst = mapa_shared(mbar_u, rr);

    __syncthreads();
    cluster_barrier();   // mbarrier init + initial expects visible before stores

    const float* Ub = U  + (size_t)batch * TT * S;
    float*       Hb = HS + (size_t)batch * TT * S;

    float4 un0 = *(const float4*)&Ub[wcol];
    float4 un1 = *(const float4*)&Ub[wcol + 4];
    float4 up0 = make_float4(0.f, 0.f, 0.f, 0.f);
    float4 up1 = make_float4(0.f, 0.f, 0.f, 0.f);

    for (int t = 0; t < TT; t++) {
        const int m   = t & 1;
        const int par = (t >> 1) & 1;

        const float4 uc0 = un0, uc1 = un1;
        {   // prefetch next step's u
            int tn = (t + 1 < TT) ? (t + 1) : t;
            un0 = *(const float4*)&Ub[(size_t)tn * S + wcol];
            un1 = *(const float4*)&Ub[(size_t)tn * S + wcol + 4];
        }

        // h pairs (ulonglong2 = LDS.128)
        ull hp[4][2];
#pragma unroll
        for (int r = 0; r < 4; r++) {
            ulonglong2 hv = *(const ulonglong2*)&h_sm[4 * lane + 128 * r];
            hp[r][0] = hv.x; hp[r][1] = hv.y;
        }

        ull accA[8], accK[8];
#pragma unroll
        for (int c = 0; c < 8; c++) { accA[c] = 0ull; accK[c] = 0ull; }
#pragma unroll
        for (int c = 0; c < 8; c++) {
            const float* Ac = A_sm + (size_t)(8 * w + c) * S;
#pragma unroll
            for (int r = 0; r < 4; r++) {
                ulonglong2 av = *(const ulonglong2*)&Ac[4 * lane + 128 * r];
                accA[c] = ffma2(av.x, hp[r][0], accA[c]);
                accA[c] = ffma2(av.y, hp[r][1], accA[c]);
                accK[c] = ffma2(kp[c][r][0], hp[r][0], accK[c]);
                accK[c] = ffma2(kp[c][r][1], hp[r][1], accK[c]);
            }
        }
        float z[8];
        const float upv[8] = {up0.x, up0.y, up0.z, up0.w, up1.x, up1.y, up1.z, up1.w};
        const float ucv[8] = {uc0.x, uc0.y, uc0.z, uc0.w, uc1.x, uc1.y, uc1.z, uc1.w};
#pragma unroll
        for (int c = 0; c < 8; c++) {
            float2 a = upk(accA[c]), k = upk(accK[c]);
            z[c] = (a.x + a.y) + (k.x + k.y) * upv[c];
        }
#pragma unroll
        for (int off = 16; off > 0; off >>= 1) {
#pragma unroll
            for (int c = 0; c < 8; c++)
                z[c] += __shfl_xor_sync(0xffffffffu, z[c], off);
        }
        float s1 = 0.f, s2 = 0.f;
#pragma unroll
        for (int c = 0; c < 8; c++) {
            z[c] += abv[c] + ucv[c];
            s1 += z[c];
            s2 += z[c] * z[c];
        }

        // ---- broadcast: lane L -> rank L, st.async with remote tx accounting
        if (lane < 8) {
            const uint32_t mb = mdst + (uint32_t)(m * 8);
            uint32_t zd = zdst + (uint32_t)((m * S + wcol) * 4);
            st_async_b64(zd +  0, pk(z[0], z[1]), mb);
            st_async_b64(zd +  8, pk(z[2], z[3]), mb);
            st_async_b64(zd + 16, pk(z[4], z[5]), mb);
            st_async_b64(zd + 24, pk(z[6], z[7]), mb);
            st_async_b64(pdst + (uint32_t)((m * 64 + rank * 8 + w) * 8),
                         pk(s1, s2), mb);
        }
        up0 = uc0; up1 = uc1;

        // ---- consume
        mbar_wait_parity(mbar_u + m * 8, (uint32_t)par);
        if (tid == 0) mbar_expect_tx(mbar_u + m * 8, STEP_TX_BYTES);  // re-arm t+2

        // per-warp redundant LN-sum reduction over 64 (s1,s2) partials
        float4 pp = *(const float4*)&part[m * 128 + lane * 4];
        float t1 = pp.x + pp.z, t2 = pp.y + pp.w;
#pragma unroll
        for (int off = 16; off > 0; off >>= 1) {
            t1 += __shfl_xor_sync(0xffffffffu, t1, off);
            t2 += __shfl_xor_sync(0xffffffffu, t2, off);
        }
        const float mu   = t1 * (1.f / S);
        const float rinv = rsqrtf(t2 * (1.f / S) - mu * mu + LN_EPS);

        float2 zv = *(const float2*)&zb[m * S + 2 * tid];
        float zn0 = (zv.x - mu) * rinv * g2.x + b2.x;
        float zn1 = (zv.y - mu) * rinv * g2.y + b2.y;
        hreg.x += 0.5f * zn0 * (1.f + erff(zn0 * 0.70710678118654752f));
        hreg.y += 0.5f * zn1 * (1.f + erff(zn1 * 0.70710678118654752f));
        *(float2*)&h_sm[2 * tid] = hreg;
        if (rank == 0) *(float2*)&Hb[(size_t)t * S + 2 * tid] = hreg;
        __syncthreads();   // h_sm complete before next step's matmul
    }
    cluster_barrier();     // no CTA exits while peers may still touch its smem
}

// ---------------- fp32 tiled GEMM: FFMA2 + register double-buffering ----------
// C[M,N] = A[M,K] * B[K,N], all row-major. 128x128 tile, BK=16, 256 threads,
// 8x8 microtile. Next k-tile is prefetched into registers right after the
// store-barrier, overlapping the global-load latency with the 16-kk FFMA2
// block (fix for R16's latency-bound profile: issue=42% at occ=23%).
#define BM 128
#define BN 128
#define BK 16

__global__ void __launch_bounds__(256, 2)
gemm_kernel(const float* __restrict__ A, const float* __restrict__ B,
            float* __restrict__ C, int M, int N, int Kd)
{
    __shared__ float As[BK][BM];
    __shared__ float Bs[BK][BN];

    const int t  = threadIdx.x;
    const int tx = t & 15, ty = t >> 4;
    const int m0 = blockIdx.y * BM, n0 = blockIdx.x * BN;

    // per-thread load coordinates (2 quanta each for A and B)
    const int arow0 = t >> 2,            akc0 = (t & 3) * 4;
    const int arow1 = (t + 256) >> 2,    akc1 = ((t + 256) & 3) * 4;
    const int brow0 = t >> 5,            bc0  = (t & 31) * 4;
    const int brow1 = (t + 256) >> 5,    bc1  = ((t + 256) & 31) * 4;

    ull acc2[8][4];
#pragma unroll
    for (int i = 0; i < 8; i++)
#pragma unroll
        for (int j = 0; j < 4; j++) acc2[i][j] = 0ull;

    // prologue: fetch tile k0=0 into registers
    float4 ra0 = *(const float4*)&A[(size_t)(m0 + arow0) * Kd + akc0];
    float4 ra1 = *(const float4*)&A[(size_t)(m0 + arow1) * Kd + akc1];
    float4 rb0 = *(const float4*)&B[(size_t)brow0 * N + n0 + bc0];
    float4 rb1 = *(const float4*)&B[(size_t)brow1 * N + n0 + bc1];

    for (int k0 = 0; k0 < Kd; k0 += BK) {
        // stage registers -> SMEM
        As[akc0 + 0][arow0] = ra0.x; As[akc0 + 1][arow0] = ra0.y;
        As[akc0 + 2][arow0] = ra0.z; As[akc0 + 3][arow0] = ra0.w;
        As[akc1 + 0][arow1] = ra1.x; As[akc1 + 1][arow1] = ra1.y;
        As[akc1 + 2][arow1] = ra1.z; As[akc1 + 3][arow1] = ra1.w;
        *(float4*)&Bs[brow0][bc0] = rb0;
        *(float4*)&Bs[brow1][bc1] = rb1;
        __syncthreads();

        // prefetch NEXT tile (latency overlaps the compute below)
        if (k0 + BK < Kd) {
            ra0 = *(const float4*)&A[(size_t)(m0 + arow0) * Kd + k0 + BK + akc0];
            ra1 = *(const float4*)&A[(size_t)(m0 + arow1) * Kd + k0 + BK + akc1];
            rb0 = *(const float4*)&B[(size_t)(k0 + BK + brow0) * N + n0 + bc0];
            rb1 = *(const float4*)&B[(size_t)(k0 + BK + brow1) * N + n0 + bc1];
        }

#pragma unroll
        for (int kk = 0; kk < BK; kk++) {
            ulonglong2 bq0 = *(const ulonglong2*)&Bs[kk][tx * 4];
            ulonglong2 bq1 = *(const ulonglong2*)&Bs[kk][tx * 4 + 64];
            ull bp[4] = {bq0.x, bq0.y, bq1.x, bq1.y};
            float4 a0 = *(const float4*)&As[kk][ty * 4];
            float4 a1 = *(const float4*)&As[kk][ty * 4 + 64];
            float av[8] = {a0.x, a0.y, a0.z, a0.w, a1.x, a1.y, a1.z, a1.w};
#pragma unroll
            for (int i = 0; i < 8; i++) {
                ull ad = pk(av[i], av[i]);      // duplicate a into both halves
#pragma unroll
                for (int j = 0; j < 4; j++)
                    acc2[i][j] = ffma2(ad, bp[j], acc2[i][j]);
            }
        }
        __syncthreads();
    }

#pragma unroll
    for (int i = 0; i < 8; i++) {
        int row = m0 + ((i < 4) ? (ty * 4 + i) : (64 + ty * 4 + (i - 4)));
        float2 c0 = upk(acc2[i][0]), c1 = upk(acc2[i][1]);
        float2 c2 = upk(acc2[i][2]), c3 = upk(acc2[i][3]);
        *(float4*)&C[(size_t)row * N + n0 + tx * 4]      = make_float4(c0.x, c0.y, c1.x, c1.y);
        *(float4*)&C[(size_t)row * N + n0 + 64 + tx * 4] = make_float4(c2.x, c2.y, c3.x, c3.y);
    }
}

// ---------------- launch ------------------------------------------------------
extern "C" void kernel_launch(void* const* d_in, const int* in_sizes, int n_in,
                              void* d_out, int out_size)
{
    (void)in_sizes; (void)n_in; (void)out_size;
    const float* x   = (const float*)d_in[0];
    const float* A0  = (const float*)d_in[1];
    const float* B0  = (const float*)d_in[2];
    const float* C0  = (const float*)d_in[3];
    const float* K0  = (const float*)d_in[4];
    const float* ab0 = (const float*)d_in[5];
    const float* g0  = (const float*)d_in[6];
    const float* bt0 = (const float*)d_in[7];
    const float* A1  = (const float*)d_in[8];
    const float* B1  = (const float*)d_in[9];
    const float* C1  = (const float*)d_in[10];
    const float* K1  = (const float*)d_in[11];
    const float* ab1 = (const float*)d_in[12];
    const float* g1  = (const float*)d_in[13];
    const float* bt1 = (const float*)d_in[14];
    float* out = (float*)d_out;

    float *U, *H, *W01;
    cudaGetSymbolAddress((void**)&U,   g_bufU);
    cudaGetSymbolAddress((void**)&H,   g_bufH);
    cudaGetSymbolAddress((void**)&W01, g_W01);

    cudaFuncSetAttribute(scan_kernel, cudaFuncAttributeMaxDynamicSharedMemorySize,
                         (int)SCAN_SMEM);

    const int M = NB * TT;                        // 32768
    dim3 gBig(S / BN, M / BM);                    // (4, 256)
    dim3 gSmall(S / BN, S / BM);                  // (4, 4)

    // W01 = C0 @ B1   (fuse the inter-layer GEMM pair: (hs@C0)@B1 = hs@(C0@B1))
    gemm_kernel<<<gSmall, 256>>>(C0, B1, W01, S, S, S);
    // U = x @ B0
    gemm_kernel<<<gBig, 256>>>(x, B0, U, M, S, S);
    // layer 0 scan -> H
    scan_kernel<<<NB * CLU, NTHR, SCAN_SMEM>>>(A0, K0, ab0, g0, bt0, U, H);
    // U = H @ W01
    gemm_kernel<<<gBig, 256>>>(H, W01, U, M, S, S);
    // layer 1 scan -> H
    scan_kernel<<<NB * CLU, NTHR, SCAN_SMEM>>>(A1, K1, ab1, g1, bt1, U, H);
    // out = H @ C1
    gemm_kernel<<<gBig, 256>>>(H, C1, out, M, S, S);
}